// round 15
// baseline (speedup 1.0000x reference)
#include <cuda_runtime.h>
#include <cuda_bf16.h>
#include <cstdint>

#define N_SAMP 256
#define IN_F   1024
#define B_F    128
#define C_F    16
#define J_F    (B_F * C_F)   // 2048
#define OUT_W  (IN_F + B_F)  // 1152

// ---------------- scratch (no allocs allowed) ----------------
__device__ float          g_mat[B_F * N_SAMP * C_F];   // [b][n][c] fp32, 2MB
__device__ __nv_bfloat16  g_xb[N_SAMP * IN_F];         // x bf16 [256][1024]
__device__ __nv_bfloat16  g_Tb[IN_F * J_F];            // T bf16 [1024][2048] (same layout)

__device__ __forceinline__ uint32_t smem_u32(const void* p) {
    uint32_t a;
    asm("{ .reg .u64 t; cvta.to.shared.u64 t, %1; cvt.u32.u64 %0, t; }" : "=r"(a) : "l"(p));
    return a;
}

// ---------------------------------------------------------------------------
// prep: streaming converts, no transpose.
//   blocks [0,512):   T fp32 -> g_Tb bf16 (same layout).
//                     T = 2,097,152 floats = 524,288 float4 = 512 blk * 256 thr * 4
//   blocks [512,576): x fp32 -> g_xb bf16 AND copy x -> out[:,0:1024]
//                     x = 262,144 floats = 65,536 float4 = 64 blk * 256 thr * 4
// ---------------------------------------------------------------------------
__global__ __launch_bounds__(256) void prep_kernel(const float* __restrict__ x,
                                                   const float* __restrict__ T,
                                                   float* __restrict__ out) {
    const int tid = threadIdx.x;
    if (blockIdx.x < 512) {
        const int base = blockIdx.x * 1024 + tid;      // float4 index into T
        #pragma unroll
        for (int i = 0; i < 4; i++) {
            const int idx = base + i * 256;            // < 524288
            float4 v = ((const float4*)T)[idx];
            __nv_bfloat162 lo = __floats2bfloat162_rn(v.x, v.y);
            __nv_bfloat162 hi = __floats2bfloat162_rn(v.z, v.w);
            ((uint2*)g_Tb)[idx] = make_uint2(*(uint32_t*)&lo, *(uint32_t*)&hi);
        }
    } else {
        const int base = (blockIdx.x - 512) * 1024 + tid;  // float4 index into x
        #pragma unroll
        for (int i = 0; i < 4; i++) {
            const int idx = base + i * 256;            // < 65536
            float4 v = ((const float4*)x)[idx];
            const int n = idx >> 8, c4 = idx & 255;
            ((float4*)(out + n * OUT_W))[c4] = v;
            __nv_bfloat162 lo = __floats2bfloat162_rn(v.x, v.y);
            __nv_bfloat162 hi = __floats2bfloat162_rn(v.z, v.w);
            ((uint2*)g_xb)[idx] = make_uint2(*(uint32_t*)&lo, *(uint32_t*)&hi);
        }
    }
}

// ---------------------------------------------------------------------------
// bf16 MMA GEMM: g_mat scatter of C[n][j] = sum_k xb[n][k]*Tb[k][j]
// BM=BN=BK=64 -> grid (32,4) = 128 CTAs. 8 warps = 2(M) x 4(N), warp tile
// 32x16. A frag: ldmatrix.x4 from [m][k]; B frag: ldmatrix.x4.trans from
// [k][n]. Rows padded to 72 bf16 (144B). Double-buffered.
// ---------------------------------------------------------------------------
#define BM 64
#define BN 64
#define BK 64
#define KIT (IN_F / BK)   // 16

__global__ __launch_bounds__(256, 1) void gemm_kernel() {
    __shared__ __align__(16) __nv_bfloat16 As[2][BM][BK + 8];  // [m][k]
    __shared__ __align__(16) __nv_bfloat16 Bs[2][BK][BN + 8];  // [k][n]

    const int tid  = threadIdx.x;
    const int wid  = tid >> 5;
    const int lane = tid & 31;
    const int bn   = blockIdx.x;     // 0..31
    const int bm   = blockIdx.y;     // 0..3
    const int wm   = wid >> 2;       // 0..1
    const int wn   = wid & 3;        // 0..3

    const __nv_bfloat16* Axb = g_xb + (size_t)(bm * BM) * IN_F;
    const __nv_bfloat16* Tbb = g_Tb + bn * BN;

    // staging: 512 uint4 (8 bf16 each) per operand per stage, 2/thread each
    auto stage = [&](int buf, int kt) {
        #pragma unroll
        for (int i = 0; i < 2; i++) {
            const int idx = tid + i * 256;          // 0..511
            const int row = idx >> 3, seg = (idx & 7) * 8;
            *(uint4*)&As[buf][row][seg] =
                *(const uint4*)(Axb + (size_t)row * IN_F + kt + seg);
            *(uint4*)&Bs[buf][row][seg] =
                *(const uint4*)(Tbb + (size_t)(kt + row) * J_F + seg);
        }
    };

    float acc[2][2][4] = {};

    stage(0, 0);
    __syncthreads();

    for (int it = 0; it < KIT; it++) {
        const int buf = it & 1;
        if (it + 1 < KIT) stage(buf ^ 1, (it + 1) * BK);

        #pragma unroll
        for (int ks = 0; ks < 4; ks++) {
            uint32_t a[2][4];
            const int sub  = lane >> 3;
            const int arow = (sub & 1) * 8 + (lane & 7);
            const int acol = ks * 16 + (sub >> 1) * 8;
            #pragma unroll
            for (int mf = 0; mf < 2; mf++) {
                uint32_t addr = smem_u32(&As[buf][wm * 32 + mf * 16 + arow][acol]);
                asm volatile("ldmatrix.sync.aligned.m8n8.x4.shared.b16 {%0,%1,%2,%3}, [%4];"
                             : "=r"(a[mf][0]), "=r"(a[mf][1]), "=r"(a[mf][2]), "=r"(a[mf][3])
                             : "r"(addr));
            }
            uint32_t b[4];
            {
                const int brow = ks * 16 + (lane & 15);
                const int bcol = wn * 16 + (lane >> 4) * 8;
                uint32_t addr = smem_u32(&Bs[buf][brow][bcol]);
                asm volatile("ldmatrix.sync.aligned.m8n8.x4.trans.shared.b16 {%0,%1,%2,%3}, [%4];"
                             : "=r"(b[0]), "=r"(b[1]), "=r"(b[2]), "=r"(b[3])
                             : "r"(addr));
            }
            #pragma unroll
            for (int mf = 0; mf < 2; mf++)
                #pragma unroll
                for (int nf = 0; nf < 2; nf++)
                    asm volatile(
                        "mma.sync.aligned.m16n8k16.row.col.f32.bf16.bf16.f32 "
                        "{%0,%1,%2,%3}, {%4,%5,%6,%7}, {%8,%9}, {%0,%1,%2,%3};"
                        : "+f"(acc[mf][nf][0]), "+f"(acc[mf][nf][1]),
                          "+f"(acc[mf][nf][2]), "+f"(acc[mf][nf][3])
                        : "r"(a[mf][0]), "r"(a[mf][1]), "r"(a[mf][2]), "r"(a[mf][3]),
                          "r"(b[nf * 2]), "r"(b[nf * 2 + 1]));
        }
        __syncthreads();
    }

    // Epilogue: scatter into g_mat[b][n][c], b = j>>4, c = j&15
    const int g  = lane >> 2;
    const int cc = (lane & 3) * 2;
    #pragma unroll
    for (int mf = 0; mf < 2; mf++) {
        const int row0 = bm * BM + wm * 32 + mf * 16 + g;
        #pragma unroll
        for (int nf = 0; nf < 2; nf++) {
            const int j  = bn * BN + wn * 16 + nf * 8 + cc;
            const int bb = j >> 4;
            const int c  = j & 15;
            float* dst = g_mat + bb * (N_SAMP * C_F);
            *(float2*)(dst + row0 * C_F + c) =
                make_float2(acc[mf][nf][0], acc[mf][nf][1]);
            *(float2*)(dst + (row0 + 8) * C_F + c) =
                make_float2(acc[mf][nf][2], acc[mf][nf][3]);
        }
    }
}

// ---------------------------------------------------------------------------
// Pairwise (unchanged): 8-group triangle bound, analytic self term.
// grid (128 b, 2 n-halves), block 512 = 128 n x 4 m-quarters.
// ---------------------------------------------------------------------------
__global__ __launch_bounds__(512) void pair_kernel(float* __restrict__ out) {
    __shared__ float  sm[N_SAMP][C_F];      // 16 KB
    __shared__ float4 sg[N_SAMP][2];        // 8 KB
    __shared__ float  red[3][128];

    const int b   = blockIdx.x;
    const int tid = threadIdx.x;
    const float* mb = g_mat + b * (N_SAMP * C_F);

    #pragma unroll
    for (int r = 0; r < 2; r++) {
        int i = tid + r * 512;
        ((float4*)sm)[i] = ((const float4*)mb)[i];
    }
    __syncthreads();

    {
        const int r = tid >> 1, h = tid & 1;
        const float4 p = *(const float4*)&sm[r][h * 8];
        const float4 q = *(const float4*)&sm[r][h * 8 + 4];
        sg[r][h] = make_float4(p.x + p.y, p.z + p.w, q.x + q.y, q.z + q.w);
    }
    __syncthreads();

    const int nl = tid & 127;
    const int q  = tid >> 7;
    const int n  = blockIdx.y * 128 + nl;

    const float4 a0 = *(const float4*)&sm[n][0];
    const float4 a1 = *(const float4*)&sm[n][4];
    const float4 a2 = *(const float4*)&sm[n][8];
    const float4 a3 = *(const float4*)&sm[n][12];
    const float4 mg0 = sg[n][0];
    const float4 mg1 = sg[n][1];

    float acc = 0.f;
    const int m0 = q * 64;
    #pragma unroll 4
    for (int m = m0; m < m0 + 64; m++) {
        const float4 g0 = sg[m][0];
        const float4 g1 = sg[m][1];
        float bnd;
        bnd  = fabsf(mg0.x - g0.x) + fabsf(mg0.y - g0.y);
        bnd += fabsf(mg0.z - g0.z) + fabsf(mg0.w - g0.w);
        bnd += fabsf(mg1.x - g1.x) + fabsf(mg1.y - g1.y);
        bnd += fabsf(mg1.z - g1.z) + fabsf(mg1.w - g1.w);
        const bool hit = (bnd < 40.f) && (m != n);
        if (__any_sync(0xFFFFFFFFu, hit)) {
            const float4 v0 = *(const float4*)&sm[m][0];
            const float4 v1 = *(const float4*)&sm[m][4];
            const float4 v2 = *(const float4*)&sm[m][8];
            const float4 v3 = *(const float4*)&sm[m][12];
            float d = 0.f;
            d += fabsf(a0.x - v0.x); d += fabsf(a0.y - v0.y);
            d += fabsf(a0.z - v0.z); d += fabsf(a0.w - v0.w);
            d += fabsf(a1.x - v1.x); d += fabsf(a1.y - v1.y);
            d += fabsf(a1.z - v1.z); d += fabsf(a1.w - v1.w);
            d += fabsf(a2.x - v2.x); d += fabsf(a2.y - v2.y);
            d += fabsf(a2.z - v2.z); d += fabsf(a2.w - v2.w);
            d += fabsf(a3.x - v3.x); d += fabsf(a3.y - v3.y);
            d += fabsf(a3.z - v3.z); d += fabsf(a3.w - v3.w);
            if (m != n) acc += __expf(-d);
        }
    }

    if (q > 0) red[q - 1][nl] = acc;
    __syncthreads();
    if (q == 0)
        out[n * OUT_W + IN_F + b] =
            1.0f + acc + red[0][nl] + red[1][nl] + red[2][nl];
}

// ---------------------------------------------------------------------------
extern "C" void kernel_launch(void* const* d_in, const int* in_sizes, int n_in,
                              void* d_out, int out_size) {
    const float* x = (const float*)d_in[0];   // [256, 1024]
    const float* T = (const float*)d_in[1];   // [1024, 128, 16]
    float* out = (float*)d_out;               // [256, 1152]

    prep_kernel<<<576, 256>>>(x, T, out);
    gemm_kernel<<<dim3(J_F / BN, N_SAMP / BM), 256>>>();
    pair_kernel<<<dim3(B_F, 2), 512>>>(out);
}